// round 11
// baseline (speedup 1.0000x reference)
#include <cuda_runtime.h>

#define Bb 8
#define Ll 512
#define Dd 256
#define Uu 32
#define TS 16      // s-rows per block in the fused kernel
#define PAD 20     // padded row stride (floats) of weight tile [t][s]
#define RSTRIDE 17 // u64 stride of the reduction buffer (bank-conflict pad)

// scratch: Eq = exp2(C*(q+bh)) and Ek = exp2(C*k), [B*L, U], C = 2*log2(e)
__device__ float g_q[Bb * Ll * Uu];
__device__ float g_k[Bb * Ll * Uu];

__device__ __forceinline__ float fast_ex2(float x) {
    float y; asm("ex2.approx.f32 %0, %1;" : "=f"(y) : "f"(x)); return y;
}
__device__ __forceinline__ float fast_rcp(float x) {
    float y; asm("rcp.approx.f32 %0, %1;" : "=f"(y) : "f"(x)); return y;
}
__device__ __forceinline__ unsigned long long pack2(float lo, float hi) {
    unsigned long long r;
    asm("mov.b64 %0, {%1, %2};" : "=l"(r) : "f"(lo), "f"(hi));
    return r;
}
__device__ __forceinline__ void unpack2(float& lo, float& hi, unsigned long long v) {
    asm("mov.b64 {%0, %1}, %2;" : "=f"(lo), "=f"(hi) : "l"(v));
}
__device__ __forceinline__ void fma2(unsigned long long& d, unsigned long long a,
                                     unsigned long long b) {
    asm("fma.rn.f32x2 %0, %1, %2, %0;" : "+l"(d) : "l"(a), "l"(b));
}
__device__ __forceinline__ void add2(unsigned long long& d, unsigned long long a) {
    asm("add.rn.f32x2 %0, %0, %1;" : "+l"(d) : "l"(a));
}
__device__ __forceinline__ void mul2(unsigned long long& d, unsigned long long a) {
    asm("mul.rn.f32x2 %0, %0, %1;" : "+l"(d) : "l"(a));
}

// ---------------------------------------------------------------------------
// Kernel 1: q/k projections + exp factoring (unchanged, known-good)
// ---------------------------------------------------------------------------
__global__ __launch_bounds__(256) void qk_kernel(const float* __restrict__ x,
                                                 const float* __restrict__ Wt,
                                                 const float* __restrict__ Wx,
                                                 const float* __restrict__ bh) {
    __shared__ float xs[8 * Dd];
    const int row0 = blockIdx.x * 8;

    const float4* xg = (const float4*)(x + (size_t)row0 * Dd);
    float4* xs4 = (float4*)xs;
    xs4[threadIdx.x] = xg[threadIdx.x];
    xs4[threadIdx.x + 256] = xg[threadIdx.x + 256];
    __syncthreads();

    const int u = threadIdx.x & 31;
    const int which = (threadIdx.x >> 5) & 1;
    const int rp = threadIdx.x >> 6;
    const float* __restrict__ W = which ? Wx : Wt;

    float acc0 = which ? 0.f : bh[u];
    float acc1 = acc0;
    const float* xr0 = xs + rp * Dd;
    const float* xr1 = xs + (rp + 4) * Dd;

#pragma unroll 8
    for (int d = 0; d < Dd; d++) {
        float w = W[d * Uu + u];
        acc0 = fmaf(xr0[d], w, acc0);
        acc1 = fmaf(xr1[d], w, acc1);
    }

    const float C2LOG2E = 2.8853900817779268f;  // 2*log2(e)
    float* dst = which ? g_k : g_q;
    dst[(row0 + rp) * Uu + u] = fast_ex2(C2LOG2E * acc0);
    dst[(row0 + rp + 4) * Uu + u] = fast_ex2(C2LOG2E * acc1);
}

// ---------------------------------------------------------------------------
// Phase A (producer warps): one t-row, 8 s-rows (s-half sh).
// w[t][s] = exp(alpha), alpha = sumWa - 2*sum_u Wa_u/(1+Eq*Ek).
// ---------------------------------------------------------------------------
__device__ __forceinline__ void phaseA(float* __restrict__ sa,
                                       const float* __restrict__ sq,
                                       const float4* __restrict__ swa4,
                                       const float* __restrict__ gkb,
                                       int t, int sh, float swl) {
    float acc[8];
#pragma unroll
    for (int s = 0; s < 8; s++) acc[s] = 0.f;

    const float4* kg = (const float4*)(gkb + (size_t)t * Uu);
    const float* qb = sq + sh * 8 * Uu;

#pragma unroll
    for (int i = 0; i < 8; i++) {
        float4 kv = kg[i];
        float4 w4 = swa4[i];
#pragma unroll
        for (int s = 0; s < 8; s++) {
            float4 q4 = *(const float4*)(qb + s * Uu + 4 * i);  // broadcast LDS
            acc[s] = fmaf(w4.x, fast_rcp(fmaf(kv.x, q4.x, 1.f)), acc[s]);
            acc[s] = fmaf(w4.y, fast_rcp(fmaf(kv.y, q4.y, 1.f)), acc[s]);
            acc[s] = fmaf(w4.z, fast_rcp(fmaf(kv.z, q4.z, 1.f)), acc[s]);
            acc[s] = fmaf(w4.w, fast_rcp(fmaf(kv.w, q4.w, 1.f)), acc[s]);
        }
    }

    const float M2L = -2.8853900817779268f;  // -2*log2(e)
    float* o = sa + t * PAD + sh * 8;
#pragma unroll
    for (int s = 0; s < 8; s++) o[s] = fast_ex2(fmaf(M2L, acc[s], swl));
}

// ---------------------------------------------------------------------------
// Phase C (consumer warps): thread owns a d-pair, all 16 s; 64 t-steps.
// ---------------------------------------------------------------------------
__device__ __forceinline__ void phaseC(unsigned long long* __restrict__ acc,
                                       const float* __restrict__ sa,
                                       const float* __restrict__ xb, int t0) {
#pragma unroll 4
    for (int t = t0; t < t0 + 64; t++) {
        float2 xv = *(const float2*)(xb + (size_t)t * Dd);  // coalesced LDG.64
        unsigned long long xx0 = pack2(xv.x, xv.x);
        unsigned long long xx1 = pack2(xv.y, xv.y);

        const float* r = sa + t * PAD;
        ulonglong2 p0 = *(const ulonglong2*)(r);       // broadcast LDS.128
        ulonglong2 p1 = *(const ulonglong2*)(r + 4);
        ulonglong2 p2 = *(const ulonglong2*)(r + 8);
        ulonglong2 p3 = *(const ulonglong2*)(r + 12);

        fma2(acc[0],  p0.x, xx0); fma2(acc[1],  p0.x, xx1);
        fma2(acc[2],  p0.y, xx0); fma2(acc[3],  p0.y, xx1);
        fma2(acc[4],  p1.x, xx0); fma2(acc[5],  p1.x, xx1);
        fma2(acc[6],  p1.y, xx0); fma2(acc[7],  p1.y, xx1);
        fma2(acc[8],  p2.x, xx0); fma2(acc[9],  p2.x, xx1);
        fma2(acc[10], p2.y, xx0); fma2(acc[11], p2.y, xx1);
        fma2(acc[12], p3.x, xx0); fma2(acc[13], p3.x, xx1);
        fma2(acc[14], p3.y, xx0); fma2(acc[15], p3.y, xx1);
    }
}

// ---------------------------------------------------------------------------
// Kernel 2: warp-specialized producer/consumer pipeline.
//   warps 0-7  (A-group): compute w = exp(alpha) chunk by chunk (MUFU pipe)
//   warps 8-15 (C-group): accumulate c += w * x on the previous chunk (FMA pipe)
//   segments: A0 | A1+C0 | A2+C1 | A3+C2 | B'+C3 | reduce/scale/store
//   No-max softmax (alpha bounded by sum|Wa|); normalization via sinv in epilogue.
// ---------------------------------------------------------------------------
__global__ __launch_bounds__(512, 2) void attn_kernel(const float* __restrict__ x,
                                                      const float* __restrict__ Wa,
                                                      float* __restrict__ out) {
    __shared__ __align__(16) float sa[Ll * PAD];  // 40 KB: w tile [t][s] / reduce buf
    __shared__ __align__(16) float sq[TS * Uu];   // 2 KB
    __shared__ float swa[Uu];
    __shared__ float sinv[TS];

    const int tid = threadIdx.x;
    const int b = blockIdx.x >> 5;
    const int s0 = (blockIdx.x & 31) * TS;

    sq[tid] = g_q[((size_t)b * Ll + s0) * Uu + tid];  // 512 = TS*Uu exactly
    if (tid < Uu) swa[tid] = Wa[tid];
    __syncthreads();

    float sumwa = 0.f;
#pragma unroll
    for (int u = 0; u < Uu; u++) sumwa += swa[u];
    const float swl = sumwa * 1.4426950408889634f;  // sumwa * log2(e)

    const bool isA = tid < 256;                     // warp-uniform split

    // A-group indexing: t within chunk, s-half
    const int tA = tid & 127;
    const int sh = (tid >> 7) & 1;
    const float* gkb = g_k + (size_t)b * Ll * Uu;
    const float4* swa4 = (const float4*)swa;

    // C-group indexing: d-pair, t-half within chunk
    const int ct = tid & 255;       // tid-256 for C threads
    const int dp = ct & 127;
    const int th = ct >> 7;
    const int d = dp * 2;
    const float* __restrict__ xb = x + (size_t)b * Ll * Dd + d;

    unsigned long long acc[16];
#pragma unroll
    for (int j = 0; j < 16; j++) acc[j] = 0ull;

    // ---- pipeline ----
    if (isA) phaseA(sa, sq, swa4, gkb, 0 * 128 + tA, sh, swl);
    __syncthreads();

    if (isA) phaseA(sa, sq, swa4, gkb, 1 * 128 + tA, sh, swl);
    else     phaseC(acc, sa, xb, 0 * 128 + th * 64);
    __syncthreads();

    if (isA) phaseA(sa, sq, swa4, gkb, 2 * 128 + tA, sh, swl);
    else     phaseC(acc, sa, xb, 1 * 128 + th * 64);
    __syncthreads();

    if (isA) phaseA(sa, sq, swa4, gkb, 3 * 128 + tA, sh, swl);
    else     phaseC(acc, sa, xb, 2 * 128 + th * 64);
    __syncthreads();

    // last segment: A-group does row sums (B'), C-group finishes C(3)
    if (isA) {
        const int w = tid >> 5;     // 0..7, each warp handles 2 s-rows
        const int lane = tid & 31;
#pragma unroll
        for (int r = 0; r < 2; r++) {
            const int srow = w * 2 + r;
            float ss = 0.f;
#pragma unroll
            for (int i = 0; i < 16; i++) ss += sa[(lane + 32 * i) * PAD + srow];
#pragma unroll
            for (int off = 16; off > 0; off >>= 1)
                ss += __shfl_xor_sync(0xffffffffu, ss, off);
            if (lane == 0) sinv[srow] = fast_rcp(ss);
        }
    } else {
        phaseC(acc, sa, xb, 3 * 128 + th * 64);
    }
    __syncthreads();  // sa now reusable; sinv visible

    // ---- reduce the two t-halves, scale by sinv, store (C-group only) ----
    {
        unsigned long long* red = (unsigned long long*)sa;

        if (!isA && th == 1) {
            unsigned long long* dst = red + dp * RSTRIDE;
#pragma unroll
            for (int j = 0; j < 16; j++) dst[j] = acc[j];
        }
        __syncthreads();

        if (!isA && th == 0) {
            const unsigned long long* src = red + dp * RSTRIDE;
#pragma unroll
            for (int j = 0; j < 16; j++) add2(acc[j], src[j]);

            float* ob = out + ((size_t)b * Ll + s0) * Dd + d;
#pragma unroll
            for (int jp = 0; jp < 8; jp++) {
                unsigned long long sc = pack2(sinv[2 * jp], sinv[2 * jp + 1]);
                mul2(acc[2 * jp + 0], sc);
                mul2(acc[2 * jp + 1], sc);
                float lo0, hi0, lo1, hi1;
                unpack2(lo0, hi0, acc[2 * jp + 0]);  // col d  : s=2jp, 2jp+1
                unpack2(lo1, hi1, acc[2 * jp + 1]);  // col d+1
                *(float2*)(ob + (2 * jp + 0) * Dd) = make_float2(lo0, lo1);
                *(float2*)(ob + (2 * jp + 1) * Dd) = make_float2(hi0, hi1);
            }
        }
    }
}

// ---------------------------------------------------------------------------
extern "C" void kernel_launch(void* const* d_in, const int* in_sizes, int n_in,
                              void* d_out, int out_size) {
    const float* x  = (const float*)d_in[0];
    const float* Wt = (const float*)d_in[1];
    const float* Wx = (const float*)d_in[2];
    const float* bh = (const float*)d_in[3];
    const float* Wa = (const float*)d_in[4];
    // d_in[5] = ba: uniform shift of alpha -> softmax-invariant, exactly droppable
    float* out = (float*)d_out;

    qk_kernel<<<Bb * Ll / 8, 256>>>(x, Wt, Wx, bh);
    attn_kernel<<<Bb * (Ll / TS), 512>>>(x, Wa, out);
}

// round 13
// speedup vs baseline: 1.0559x; 1.0559x over previous
#include <cuda_runtime.h>

#define Bb 8
#define Ll 512
#define Dd 256
#define Uu 32
#define TS 16      // s-rows per tile
#define RSTRIDE 17 // u64 stride of the reduction buffer (bank-conflict pad)

// scratch: Eq = exp2(C*(q+bh)), Ek = exp2(C*k), [B*L, U], C = 2*log2(e)
__device__ float g_q[Bb * Ll * Uu];
__device__ float g_k[Bb * Ll * Uu];
// unnormalized softmax weights, tile-major: [(b*32+st)*512 + t][16]  (8 MB)
__device__ float g_w[Bb * 32 * Ll * TS];

__device__ __forceinline__ float fast_ex2(float x) {
    float y; asm("ex2.approx.f32 %0, %1;" : "=f"(y) : "f"(x)); return y;
}
__device__ __forceinline__ float fast_rcp(float x) {
    float y; asm("rcp.approx.f32 %0, %1;" : "=f"(y) : "f"(x)); return y;
}
__device__ __forceinline__ unsigned long long pack2(float lo, float hi) {
    unsigned long long r;
    asm("mov.b64 %0, {%1, %2};" : "=l"(r) : "f"(lo), "f"(hi));
    return r;
}
__device__ __forceinline__ void unpack2(float& lo, float& hi, unsigned long long v) {
    asm("mov.b64 {%0, %1}, %2;" : "=f"(lo), "=f"(hi) : "l"(v));
}
__device__ __forceinline__ void fma2(unsigned long long& d, unsigned long long a,
                                     unsigned long long b) {
    asm("fma.rn.f32x2 %0, %1, %2, %0;" : "+l"(d) : "l"(a), "l"(b));
}
__device__ __forceinline__ void add2(unsigned long long& d, unsigned long long a) {
    asm("add.rn.f32x2 %0, %0, %1;" : "+l"(d) : "l"(a));
}
__device__ __forceinline__ void mul2(unsigned long long& d, unsigned long long a) {
    asm("mul.rn.f32x2 %0, %0, %1;" : "+l"(d) : "l"(a));
}

// ---------------------------------------------------------------------------
// Kernel 1: q/k projections + exp factoring (unchanged, known-good)
// ---------------------------------------------------------------------------
__global__ __launch_bounds__(256) void qk_kernel(const float* __restrict__ x,
                                                 const float* __restrict__ Wt,
                                                 const float* __restrict__ Wx,
                                                 const float* __restrict__ bh) {
    __shared__ float xs[8 * Dd];
    const int row0 = blockIdx.x * 8;

    const float4* xg = (const float4*)(x + (size_t)row0 * Dd);
    float4* xs4 = (float4*)xs;
    xs4[threadIdx.x] = xg[threadIdx.x];
    xs4[threadIdx.x + 256] = xg[threadIdx.x + 256];
    __syncthreads();

    const int u = threadIdx.x & 31;
    const int which = (threadIdx.x >> 5) & 1;
    const int rp = threadIdx.x >> 6;
    const float* __restrict__ W = which ? Wx : Wt;

    float acc0 = which ? 0.f : bh[u];
    float acc1 = acc0;
    const float* xr0 = xs + rp * Dd;
    const float* xr1 = xs + (rp + 4) * Dd;

#pragma unroll 8
    for (int d = 0; d < Dd; d++) {
        float w = W[d * Uu + u];
        acc0 = fmaf(xr0[d], w, acc0);
        acc1 = fmaf(xr1[d], w, acc1);
    }

    const float C2LOG2E = 2.8853900817779268f;  // 2*log2(e)
    float* dst = which ? g_k : g_q;
    dst[(row0 + rp) * Uu + u] = fast_ex2(C2LOG2E * acc0);
    dst[(row0 + rp + 4) * Uu + u] = fast_ex2(C2LOG2E * acc1);
}

// ---------------------------------------------------------------------------
// Kernel 2a: w[t][s] = exp(alpha[s][t])  (no-max softmax numerator)
//   alpha = sumWa - 2*sum_u Wa_u / (1 + Eq[s,u]*Ek[t,u])
// grid = (b:8) x (s-tile:32) x (t-half:2) = 512 blocks, 256 threads.
// Thread owns one t-row and all 16 s; writes 64B to g_w (coalesced).
// ---------------------------------------------------------------------------
__global__ __launch_bounds__(256) void attn_a_kernel(const float* __restrict__ Wa) {
    __shared__ __align__(16) float sq[TS * Uu];  // Eq rows for this tile
    __shared__ float swa[Uu];

    const int tid = threadIdx.x;
    const int b = blockIdx.x >> 6;
    const int st = (blockIdx.x >> 1) & 31;
    const int th = blockIdx.x & 1;
    const int s0 = st * TS;
    const int tile = blockIdx.x >> 1;   // b*32 + st

    sq[tid] = g_q[((size_t)b * Ll + s0) * Uu + tid];
    sq[tid + 256] = g_q[((size_t)b * Ll + s0) * Uu + tid + 256];
    if (tid < Uu) swa[tid] = Wa[tid];
    __syncthreads();

    float sumwa = 0.f;
#pragma unroll
    for (int u = 0; u < Uu; u++) sumwa += swa[u];
    const float swl = sumwa * 1.4426950408889634f;  // sumwa * log2(e)

    const int t = th * 256 + tid;
    float kk[32];
    const float4* kg = (const float4*)(g_k + ((size_t)b * Ll + t) * Uu);
#pragma unroll
    for (int i = 0; i < 8; i++) {
        float4 kv = kg[i];
        kk[4 * i + 0] = kv.x; kk[4 * i + 1] = kv.y;
        kk[4 * i + 2] = kv.z; kk[4 * i + 3] = kv.w;
    }

    const float4* swa4 = (const float4*)swa;
    const float M2L = -2.8853900817779268f;  // -2*log2(e)
    float w16[TS];

#pragma unroll
    for (int s = 0; s < TS; s++) {
        const float4* eq4 = (const float4*)(sq + s * Uu);
        float acc0 = 0.f, acc1 = 0.f;
#pragma unroll
        for (int i = 0; i < 8; i++) {
            float4 q4 = eq4[i];   // broadcast LDS
            float4 w4 = swa4[i];
            acc0 = fmaf(w4.x, fast_rcp(fmaf(kk[4 * i + 0], q4.x, 1.f)), acc0);
            acc1 = fmaf(w4.y, fast_rcp(fmaf(kk[4 * i + 1], q4.y, 1.f)), acc1);
            acc0 = fmaf(w4.z, fast_rcp(fmaf(kk[4 * i + 2], q4.z, 1.f)), acc0);
            acc1 = fmaf(w4.w, fast_rcp(fmaf(kk[4 * i + 3], q4.w, 1.f)), acc1);
        }
        w16[s] = fast_ex2(fmaf(M2L, acc0 + acc1, swl));
    }

    // coalesced: warp writes 2 KB contiguous
    float4* wd = (float4*)(g_w + ((size_t)tile * Ll + t) * TS);
#pragma unroll
    for (int j = 0; j < 4; j++)
        wd[j] = make_float4(w16[4 * j], w16[4 * j + 1], w16[4 * j + 2], w16[4 * j + 3]);
}

// ---------------------------------------------------------------------------
// Kernel 2b: c[s,:] = (1/rowsum) * sum_t w[t][s] * x[b,t,:]
// grid = (b:8) x (s-tile:32) x (d-half:2) = 512 blocks, 256 threads.
// w tile (32 KB) staged in smem; row sums computed locally; thread owns a
// d-pair and all 16 s over a t-quarter; smem tree reduction.
// ---------------------------------------------------------------------------
__global__ __launch_bounds__(256, 4) void attn_c_kernel(const float* __restrict__ x,
                                                        float* __restrict__ out) {
    __shared__ __align__(16) float sw[Ll * TS];  // 32 KB: w tile / reduce buf
    __shared__ float spart[16 * RSTRIDE];        // partial row sums
    __shared__ float ssi[TS];                    // 1/rowsum

    const int tid = threadIdx.x;
    const int b = blockIdx.x >> 6;
    const int st = (blockIdx.x >> 1) & 31;
    const int dh = blockIdx.x & 1;
    const int s0 = st * TS;
    const int tile = blockIdx.x >> 1;

    // stage w tile: straight 32 KB copy, 8 x (LDG.128 + STS.128) per thread
    {
        const float4* src = (const float4*)(g_w + (size_t)tile * Ll * TS);
        float4* dst = (float4*)sw;
#pragma unroll
        for (int i = 0; i < 8; i++)
            dst[tid + 256 * i] = src[tid + 256 * i];
    }
    __syncthreads();

    // row sums: thread (s = tid&15, chunk = tid>>4) sums 32 t's
    {
        const int s = tid & 15;
        const int ch = tid >> 4;
        float v = 0.f;
#pragma unroll 8
        for (int i = 0; i < 32; i++) v += sw[(ch * 32 + i) * TS + s];
        spart[ch * RSTRIDE + s] = v;   // RSTRIDE floats here (pad reuse)
    }
    __syncthreads();
    if (tid < TS) {
        float ss = 0.f;
#pragma unroll
        for (int c = 0; c < 16; c++) ss += spart[c * RSTRIDE + tid];
        ssi[tid] = fast_rcp(ss);
    }
    // no sync needed yet: ssi consumed only after the next __syncthreads

    // main loop: dp = d-pair within this d-half, tq = t-quarter
    const int dp = tid & 63;
    const int tq = tid >> 6;
    const int d = dh * 128 + dp * 2;
    const float* __restrict__ xb = x + (size_t)b * Ll * Dd + d;

    unsigned long long acc[16];
#pragma unroll
    for (int j = 0; j < 16; j++) acc[j] = 0ull;

    const int t0 = tq * 128;
#pragma unroll 4
    for (int t = t0; t < t0 + 128; t++) {
        float2 xv = *(const float2*)(xb + (size_t)t * Dd);  // coalesced LDG.64
        unsigned long long xx0 = pack2(xv.x, xv.x);
        unsigned long long xx1 = pack2(xv.y, xv.y);

        const float* r = sw + t * TS;
        ulonglong2 p0 = *(const ulonglong2*)(r);       // broadcast LDS.128
        ulonglong2 p1 = *(const ulonglong2*)(r + 4);
        ulonglong2 p2 = *(const ulonglong2*)(r + 8);
        ulonglong2 p3 = *(const ulonglong2*)(r + 12);

        fma2(acc[0],  p0.x, xx0); fma2(acc[1],  p0.x, xx1);
        fma2(acc[2],  p0.y, xx0); fma2(acc[3],  p0.y, xx1);
        fma2(acc[4],  p1.x, xx0); fma2(acc[5],  p1.x, xx1);
        fma2(acc[6],  p1.y, xx0); fma2(acc[7],  p1.y, xx1);
        fma2(acc[8],  p2.x, xx0); fma2(acc[9],  p2.x, xx1);
        fma2(acc[10], p2.y, xx0); fma2(acc[11], p2.y, xx1);
        fma2(acc[12], p3.x, xx0); fma2(acc[13], p3.x, xx1);
        fma2(acc[14], p3.y, xx0); fma2(acc[15], p3.y, xx1);
    }

    __syncthreads();  // all sw reads done; ssi visible; sw reusable
    unsigned long long* red = (unsigned long long*)sw;

    // step 1: tq1 -> buf0, tq3 -> buf1; tq0 += buf0, tq2 += buf1
    if (tq & 1) {
        unsigned long long* dst = red + ((tq >> 1) * 64 + dp) * RSTRIDE;
#pragma unroll
        for (int j = 0; j < 16; j++) dst[j] = acc[j];
    }
    __syncthreads();
    if (!(tq & 1)) {
        const unsigned long long* src = red + ((tq >> 1) * 64 + dp) * RSTRIDE;
#pragma unroll
        for (int j = 0; j < 16; j++) add2(acc[j], src[j]);
    }
    __syncthreads();

    // step 2: tq2 -> buf0; tq0 += buf0
    if (tq == 2) {
        unsigned long long* dst = red + dp * RSTRIDE;
#pragma unroll
        for (int j = 0; j < 16; j++) dst[j] = acc[j];
    }
    __syncthreads();
    if (tq == 0) {
        const unsigned long long* src = red + dp * RSTRIDE;
#pragma unroll
        for (int j = 0; j < 16; j++) add2(acc[j], src[j]);

        float* ob = out + ((size_t)b * Ll + s0) * Dd + d;
#pragma unroll
        for (int jp = 0; jp < 8; jp++) {
            unsigned long long sc = pack2(ssi[2 * jp], ssi[2 * jp + 1]);
            mul2(acc[2 * jp + 0], sc);
            mul2(acc[2 * jp + 1], sc);
            float lo0, hi0, lo1, hi1;
            unpack2(lo0, hi0, acc[2 * jp + 0]);  // col d  : s=2jp, 2jp+1
            unpack2(lo1, hi1, acc[2 * jp + 1]);  // col d+1
            *(float2*)(ob + (2 * jp + 0) * Dd) = make_float2(lo0, lo1);
            *(float2*)(ob + (2 * jp + 1) * Dd) = make_float2(hi0, hi1);
        }
    }
}

// ---------------------------------------------------------------------------
extern "C" void kernel_launch(void* const* d_in, const int* in_sizes, int n_in,
                              void* d_out, int out_size) {
    const float* x  = (const float*)d_in[0];
    const float* Wt = (const float*)d_in[1];
    const float* Wx = (const float*)d_in[2];
    const float* bh = (const float*)d_in[3];
    const float* Wa = (const float*)d_in[4];
    // d_in[5] = ba: uniform shift of alpha -> softmax-invariant, exactly droppable
    float* out = (float*)d_out;

    qk_kernel<<<Bb * Ll / 8, 256>>>(x, Wt, Wx, bh);
    attn_a_kernel<<<Bb * 32 * 2, 256>>>(Wa);
    attn_c_kernel<<<Bb * 32 * 2, 256>>>(x, out);
}